// round 1
// baseline (speedup 1.0000x reference)
#include <cuda_runtime.h>

// Problem constants
#define DIMM   512
#define NTOK   8192         // B * N = 4 * 2048
#define QKVW   1536         // 3 * INNER
#define HEADS  8
#define DHEAD  64
#define SEQN   2048
#define SCALE_F 0.125f      // 1/sqrt(64)

// Scratch (static device globals; no allocations allowed in kernel_launch)
__device__ float g_h[NTOK * DIMM];     // LayerNorm output   (16.8 MB)
__device__ float g_qkv[NTOK * QKVW];   // QKV projection     (50.3 MB)
__device__ float g_ctx[NTOK * DIMM];   // attention context  (16.8 MB)

// ---------------------------------------------------------------------------
// LayerNorm: one block (128 threads) per row of 512
// ---------------------------------------------------------------------------
__global__ void __launch_bounds__(128) ln_kernel(const float* __restrict__ x,
                                                 const float* __restrict__ gamma,
                                                 const float* __restrict__ beta,
                                                 float* __restrict__ h) {
    int row = blockIdx.x;
    int tid = threadIdx.x;
    const float* xr = x + (size_t)row * DIMM;
    float4 v = *(const float4*)(xr + tid * 4);
    float s  = v.x + v.y + v.z + v.w;
    float s2 = v.x * v.x + v.y * v.y + v.z * v.z + v.w * v.w;
#pragma unroll
    for (int off = 16; off > 0; off >>= 1) {
        s  += __shfl_xor_sync(0xffffffffu, s,  off);
        s2 += __shfl_xor_sync(0xffffffffu, s2, off);
    }
    __shared__ float red[8];
    int wid = tid >> 5;
    if ((tid & 31) == 0) { red[wid] = s; red[4 + wid] = s2; }
    __syncthreads();
    float sum  = red[0] + red[1] + red[2] + red[3];
    float sum2 = red[4] + red[5] + red[6] + red[7];
    float mean = sum * (1.0f / DIMM);
    float var  = sum2 * (1.0f / DIMM) - mean * mean;
    float rstd = rsqrtf(var + 1e-5f);
    float4 g = *(const float4*)(gamma + tid * 4);
    float4 b = *(const float4*)(beta  + tid * 4);
    float4 o;
    o.x = (v.x - mean) * rstd * g.x + b.x;
    o.y = (v.y - mean) * rstd * g.y + b.y;
    o.z = (v.z - mean) * rstd * g.z + b.z;
    o.w = (v.w - mean) * rstd * g.w + b.w;
    *(float4*)(h + (size_t)row * DIMM + tid * 4) = o;
}

// ---------------------------------------------------------------------------
// SGEMM: C[M,N] = A[M,K] @ B[K,N], all row-major fp32.
// Block tile 128x128, K-tile 16, 256 threads, 8x8 per thread.
// Requires M%128==0, N%128==0, K%16==0 (true for all call sites).
// ---------------------------------------------------------------------------
__global__ void __launch_bounds__(256) sgemm128(const float* __restrict__ A,
                                                const float* __restrict__ B,
                                                float* __restrict__ C,
                                                int M, int N, int K) {
    __shared__ float As[16][128];   // transposed: As[k][row]
    __shared__ float Bs[16][128];   // natural:    Bs[k][col]

    int tid  = threadIdx.x;
    int rowb = blockIdx.y * 128;
    int colb = blockIdx.x * 128;

    int tr = (tid >> 4) * 8;     // thread row base within tile
    int tc = (tid & 15) * 8;     // thread col base within tile

    int ar = tid >> 1;           // A-loader row (0..127)
    int ak = (tid & 1) * 8;      // A-loader k offset (0 or 8)
    int br = tid >> 5;           // B-loader row (0..7; second row +8)
    int bc = (tid & 31) * 4;     // B-loader col

    const float* Ap = A + (size_t)(rowb + ar) * K + ak;
    const float* Bp = B + colb + bc;

    float acc[8][8];
#pragma unroll
    for (int i = 0; i < 8; i++)
#pragma unroll
        for (int j = 0; j < 8; j++) acc[i][j] = 0.0f;

    for (int k0 = 0; k0 < K; k0 += 16) {
        float4 a0 = *(const float4*)(Ap + k0);
        float4 a1 = *(const float4*)(Ap + k0 + 4);
        float4 b0 = *(const float4*)(Bp + (size_t)(k0 + br) * N);
        float4 b1 = *(const float4*)(Bp + (size_t)(k0 + br + 8) * N);

        As[ak + 0][ar] = a0.x; As[ak + 1][ar] = a0.y;
        As[ak + 2][ar] = a0.z; As[ak + 3][ar] = a0.w;
        As[ak + 4][ar] = a1.x; As[ak + 5][ar] = a1.y;
        As[ak + 6][ar] = a1.z; As[ak + 7][ar] = a1.w;
        *(float4*)&Bs[br][bc]     = b0;
        *(float4*)&Bs[br + 8][bc] = b1;
        __syncthreads();

#pragma unroll
        for (int k = 0; k < 16; k++) {
            float4 a0v = *(float4*)&As[k][tr];
            float4 a1v = *(float4*)&As[k][tr + 4];
            float4 b0v = *(float4*)&Bs[k][tc];
            float4 b1v = *(float4*)&Bs[k][tc + 4];
            float av[8] = {a0v.x, a0v.y, a0v.z, a0v.w, a1v.x, a1v.y, a1v.z, a1v.w};
            float bv[8] = {b0v.x, b0v.y, b0v.z, b0v.w, b1v.x, b1v.y, b1v.z, b1v.w};
#pragma unroll
            for (int i = 0; i < 8; i++)
#pragma unroll
                for (int j = 0; j < 8; j++)
                    acc[i][j] = fmaf(av[i], bv[j], acc[i][j]);
        }
        __syncthreads();
    }

#pragma unroll
    for (int i = 0; i < 8; i++) {
        float* cp = C + (size_t)(rowb + tr + i) * N + colb + tc;
        float4 o0 = {acc[i][0], acc[i][1], acc[i][2], acc[i][3]};
        float4 o1 = {acc[i][4], acc[i][5], acc[i][6], acc[i][7]};
        *(float4*)cp       = o0;
        *(float4*)(cp + 4) = o1;
    }
}

// ---------------------------------------------------------------------------
// Flash attention (fp32): one block per (bh, 64-row q-tile).
// 256 threads = 16x16; each thread owns a 4x4 register tile.
// Q and K stored d-major (transposed) in smem -> contiguous LDS.128.
// P aliases the K smem region (barrier-separated). 48 KB smem total.
// ---------------------------------------------------------------------------
__global__ void __launch_bounds__(256) attn_kernel(const float* __restrict__ qkv,
                                                   float* __restrict__ ctx) {
    __shared__ float Qs[64 * 64];   // [d][i], pre-scaled by SCALE_F
    __shared__ float KP[64 * 64];   // K: [d][j]  /  P: [i][j]
    __shared__ float Vs[64 * 64];   // [j][d]

    int tid = threadIdx.x;
    int tx = tid & 15;      // owns cols tx*4 .. tx*4+3 (j in S, d in O)
    int ty = tid >> 4;      // owns rows ty*4 .. ty*4+3
    int bh = blockIdx.y;
    int b = bh >> 3, h = bh & 7;
    int q0 = blockIdx.x * 64;

    const float* qp = qkv + (size_t)b * SEQN * QKVW + h * DHEAD;
    const float* kp = qp + 512;
    const float* vp = qp + 1024;

    // Load Q tile, transposed + pre-scaled
    {
        int i     = tid >> 2;
        int dbase = tid & 3;
        const float* src = qp + (size_t)(q0 + i) * QKVW;
#pragma unroll
        for (int c = 0; c < 4; c++) {
            int d = (dbase + 4 * c) * 4;
            float4 f = *(const float4*)(src + d);
            Qs[(d + 0) * 64 + i] = f.x * SCALE_F;
            Qs[(d + 1) * 64 + i] = f.y * SCALE_F;
            Qs[(d + 2) * 64 + i] = f.z * SCALE_F;
            Qs[(d + 3) * 64 + i] = f.w * SCALE_F;
        }
    }

    float m_i[4], l_i[4], O[4][4];
#pragma unroll
    for (int i = 0; i < 4; i++) {
        m_i[i] = -1e30f;
        l_i[i] = 0.0f;
#pragma unroll
        for (int j = 0; j < 4; j++) O[i][j] = 0.0f;
    }

    for (int t = 0; t < SEQN / 64; t++) {
        int kv0 = t * 64;
        // Load K (transposed) and V (natural)
        {
            int j     = tid >> 2;
            int dbase = tid & 3;
            const float* ks = kp + (size_t)(kv0 + j) * QKVW;
            const float* vs = vp + (size_t)(kv0 + j) * QKVW;
#pragma unroll
            for (int c = 0; c < 4; c++) {
                int d = (dbase + 4 * c) * 4;
                float4 f = *(const float4*)(ks + d);
                KP[(d + 0) * 64 + j] = f.x;
                KP[(d + 1) * 64 + j] = f.y;
                KP[(d + 2) * 64 + j] = f.z;
                KP[(d + 3) * 64 + j] = f.w;
                float4 g = *(const float4*)(vs + d);
                *(float4*)&Vs[j * 64 + d] = g;
            }
        }
        __syncthreads();

        // S = (scaled Q) @ K^T for this 64x64 tile, 4x4 per thread
        float S[4][4];
#pragma unroll
        for (int i = 0; i < 4; i++)
#pragma unroll
            for (int j = 0; j < 4; j++) S[i][j] = 0.0f;

#pragma unroll 8
        for (int d = 0; d < 64; d++) {
            float4 q = *(float4*)&Qs[d * 64 + ty * 4];
            float4 k = *(float4*)&KP[d * 64 + tx * 4];
            float qa[4] = {q.x, q.y, q.z, q.w};
            float ka[4] = {k.x, k.y, k.z, k.w};
#pragma unroll
            for (int i = 0; i < 4; i++)
#pragma unroll
                for (int j = 0; j < 4; j++)
                    S[i][j] = fmaf(qa[i], ka[j], S[i][j]);
        }

        // Online softmax row update (rows shared by 16 tx-lanes; xor 1..8
        // stays within the 16-lane group since lane = (ty&1)*16 + tx)
#pragma unroll
        for (int i = 0; i < 4; i++) {
            float m = fmaxf(fmaxf(S[i][0], S[i][1]), fmaxf(S[i][2], S[i][3]));
#pragma unroll
            for (int off = 8; off > 0; off >>= 1)
                m = fmaxf(m, __shfl_xor_sync(0xffffffffu, m, off));
            float mn   = fmaxf(m_i[i], m);
            float corr = __expf(m_i[i] - mn);
            m_i[i] = mn;
            float r = 0.0f;
#pragma unroll
            for (int j = 0; j < 4; j++) {
                S[i][j] = __expf(S[i][j] - mn);
                r += S[i][j];
            }
#pragma unroll
            for (int off = 8; off > 0; off >>= 1)
                r += __shfl_xor_sync(0xffffffffu, r, off);
            l_i[i] = l_i[i] * corr + r;
#pragma unroll
            for (int j = 0; j < 4; j++) O[i][j] *= corr;
        }

        __syncthreads();   // everyone done reading KP-as-K

        // Write P into KP
#pragma unroll
        for (int i = 0; i < 4; i++) {
            float4 p = {S[i][0], S[i][1], S[i][2], S[i][3]};
            *(float4*)&KP[(ty * 4 + i) * 64 + tx * 4] = p;
        }
        __syncthreads();

        // O += P @ V
#pragma unroll 8
        for (int jj = 0; jj < 64; jj++) {
            float4 v = *(float4*)&Vs[jj * 64 + tx * 4];
            float va[4] = {v.x, v.y, v.z, v.w};
            float pa[4];
#pragma unroll
            for (int i = 0; i < 4; i++) pa[i] = KP[(ty * 4 + i) * 64 + jj];
#pragma unroll
            for (int i = 0; i < 4; i++)
#pragma unroll
                for (int j = 0; j < 4; j++)
                    O[i][j] = fmaf(pa[i], va[j], O[i][j]);
        }
        __syncthreads();   // before next tile overwrites KP/Vs
    }

    // Normalize and store context (head-contiguous layout: [tok][h*64+d])
#pragma unroll
    for (int i = 0; i < 4; i++) {
        float inv = 1.0f / l_i[i];
        float4 o = {O[i][0] * inv, O[i][1] * inv, O[i][2] * inv, O[i][3] * inv};
        size_t row = (size_t)(b * SEQN + q0 + ty * 4 + i);
        *(float4*)&ctx[row * DIMM + h * DHEAD + tx * 4] = o;
    }
}

// ---------------------------------------------------------------------------
// kernel_launch
// ---------------------------------------------------------------------------
extern "C" void kernel_launch(void* const* d_in, const int* in_sizes, int n_in,
                              void* d_out, int out_size) {
    const float* x     = (const float*)d_in[0];
    const float* gamma = (const float*)d_in[1];
    const float* beta  = (const float*)d_in[2];
    const float* wqkv  = (const float*)d_in[3];
    const float* wout  = (const float*)d_in[4];
    float* out = (float*)d_out;

    float *h, *qkv, *ctx;
    cudaGetSymbolAddress((void**)&h,   g_h);
    cudaGetSymbolAddress((void**)&qkv, g_qkv);
    cudaGetSymbolAddress((void**)&ctx, g_ctx);

    ln_kernel<<<NTOK, 128>>>(x, gamma, beta, h);
    sgemm128<<<dim3(QKVW / 128, NTOK / 128), 256>>>(h, wqkv, qkv, NTOK, QKVW, DIMM);
    attn_kernel<<<dim3(SEQN / 64, 4 * HEADS), 256>>>(qkv, ctx);
    sgemm128<<<dim3(DIMM / 128, NTOK / 128), 256>>>(ctx, wout, out, NTOK, DIMM, DIMM);
}

// round 4
// speedup vs baseline: 1.5003x; 1.5003x over previous
#include <cuda_runtime.h>
#include <cuda_bf16.h>
#include <cstdint>

// Problem constants
#define DIMM   512
#define NTOK   8192         // B * N = 4 * 2048
#define QKVW   1536         // 3 * INNER
#define HEADS  8
#define DHEAD  64
#define SEQN   2048
#define SCALE_F 0.125f      // 1/sqrt(64)

// Scratch (static device globals; no allocations allowed anywhere)
__device__ float g_h[NTOK * DIMM];     // LayerNorm output
__device__ float g_qkv[NTOK * QKVW];   // QKV projection
__device__ float g_ctx[NTOK * DIMM];   // attention context

// ===========================================================================
// helpers
// ===========================================================================
__device__ __forceinline__ uint32_t smem_to_u32(const void* p) {
    uint32_t a;
    asm("{ .reg .u64 t; cvta.to.shared.u64 t, %1; cvt.u32.u64 %0, t; }" : "=r"(a) : "l"(p));
    return a;
}

// split-bf16 pack: returns packed(hi(a),hi(b)), writes packed(lo(a),lo(b))
__device__ __forceinline__ uint32_t pack_split(float a, float b, uint32_t& lo) {
    __nv_bfloat16 ah = __float2bfloat16(a);
    __nv_bfloat16 bh = __float2bfloat16(b);
    __nv_bfloat16 al = __float2bfloat16(a - __bfloat162float(ah));
    __nv_bfloat16 bl = __float2bfloat16(b - __bfloat162float(bh));
    lo = (uint32_t)__bfloat16_as_ushort(al) | ((uint32_t)__bfloat16_as_ushort(bl) << 16);
    return (uint32_t)__bfloat16_as_ushort(ah) | ((uint32_t)__bfloat16_as_ushort(bh) << 16);
}

__device__ __forceinline__ void mma_bf16(float* d, const uint32_t* a, uint32_t b0, uint32_t b1) {
    asm volatile("mma.sync.aligned.m16n8k16.row.col.f32.bf16.bf16.f32 "
                 "{%0,%1,%2,%3}, {%4,%5,%6,%7}, {%8,%9}, {%0,%1,%2,%3};"
                 : "+f"(d[0]), "+f"(d[1]), "+f"(d[2]), "+f"(d[3])
                 : "r"(a[0]), "r"(a[1]), "r"(a[2]), "r"(a[3]), "r"(b0), "r"(b1));
}

#define LDSM_X4(r, a) \
    asm volatile("ldmatrix.sync.aligned.m8n8.x4.shared.b16 {%0,%1,%2,%3}, [%4];" \
        : "=r"((r)[0]), "=r"((r)[1]), "=r"((r)[2]), "=r"((r)[3]) : "r"(a))
#define LDSM_X2(r0, r1, a) \
    asm volatile("ldmatrix.sync.aligned.m8n8.x2.shared.b16 {%0,%1}, [%2];" \
        : "=r"(r0), "=r"(r1) : "r"(a))
#define LDSM_X2T(r0, r1, a) \
    asm volatile("ldmatrix.sync.aligned.m8n8.x2.trans.shared.b16 {%0,%1}, [%2];" \
        : "=r"(r0), "=r"(r1) : "r"(a))

// ===========================================================================
// LayerNorm
// ===========================================================================
__global__ void __launch_bounds__(128) ln_kernel(const float* __restrict__ x,
                                                 const float* __restrict__ gamma,
                                                 const float* __restrict__ beta,
                                                 float* __restrict__ h) {
    int row = blockIdx.x;
    int tid = threadIdx.x;
    const float* xr = x + (size_t)row * DIMM;
    float4 v = *(const float4*)(xr + tid * 4);
    float s  = v.x + v.y + v.z + v.w;
    float s2 = v.x * v.x + v.y * v.y + v.z * v.z + v.w * v.w;
#pragma unroll
    for (int off = 16; off > 0; off >>= 1) {
        s  += __shfl_xor_sync(0xffffffffu, s,  off);
        s2 += __shfl_xor_sync(0xffffffffu, s2, off);
    }
    __shared__ float red[8];
    int wid = tid >> 5;
    if ((tid & 31) == 0) { red[wid] = s; red[4 + wid] = s2; }
    __syncthreads();
    float sum  = red[0] + red[1] + red[2] + red[3];
    float sum2 = red[4] + red[5] + red[6] + red[7];
    float mean = sum * (1.0f / DIMM);
    float var  = sum2 * (1.0f / DIMM) - mean * mean;
    float rstd = rsqrtf(var + 1e-5f);
    float4 g = *(const float4*)(gamma + tid * 4);
    float4 b = *(const float4*)(beta  + tid * 4);
    float4 o;
    o.x = (v.x - mean) * rstd * g.x + b.x;
    o.y = (v.y - mean) * rstd * g.y + b.y;
    o.z = (v.z - mean) * rstd * g.z + b.z;
    o.w = (v.w - mean) * rstd * g.w + b.w;
    *(float4*)(h + (size_t)row * DIMM + tid * 4) = o;
}

// ===========================================================================
// fp32 SGEMM (proven, round-1)
// ===========================================================================
__global__ void __launch_bounds__(256) sgemm128(const float* __restrict__ A,
                                                const float* __restrict__ B,
                                                float* __restrict__ C,
                                                int M, int N, int K) {
    __shared__ float As[16][128];
    __shared__ float Bs[16][128];
    int tid  = threadIdx.x;
    int rowb = blockIdx.y * 128;
    int colb = blockIdx.x * 128;
    int tr = (tid >> 4) * 8;
    int tc = (tid & 15) * 8;
    int ar = tid >> 1;
    int ak = (tid & 1) * 8;
    int br = tid >> 5;
    int bc = (tid & 31) * 4;
    const float* Ap = A + (size_t)(rowb + ar) * K + ak;
    const float* Bp = B + colb + bc;
    float acc[8][8];
#pragma unroll
    for (int i = 0; i < 8; i++)
#pragma unroll
        for (int j = 0; j < 8; j++) acc[i][j] = 0.0f;
    for (int k0 = 0; k0 < K; k0 += 16) {
        float4 a0 = *(const float4*)(Ap + k0);
        float4 a1 = *(const float4*)(Ap + k0 + 4);
        float4 b0 = *(const float4*)(Bp + (size_t)(k0 + br) * N);
        float4 b1 = *(const float4*)(Bp + (size_t)(k0 + br + 8) * N);
        As[ak + 0][ar] = a0.x; As[ak + 1][ar] = a0.y;
        As[ak + 2][ar] = a0.z; As[ak + 3][ar] = a0.w;
        As[ak + 4][ar] = a1.x; As[ak + 5][ar] = a1.y;
        As[ak + 6][ar] = a1.z; As[ak + 7][ar] = a1.w;
        *(float4*)&Bs[br][bc]     = b0;
        *(float4*)&Bs[br + 8][bc] = b1;
        __syncthreads();
#pragma unroll
        for (int k = 0; k < 16; k++) {
            float4 a0v = *(float4*)&As[k][tr];
            float4 a1v = *(float4*)&As[k][tr + 4];
            float4 b0v = *(float4*)&Bs[k][tc];
            float4 b1v = *(float4*)&Bs[k][tc + 4];
            float av[8] = {a0v.x, a0v.y, a0v.z, a0v.w, a1v.x, a1v.y, a1v.z, a1v.w};
            float bv[8] = {b0v.x, b0v.y, b0v.z, b0v.w, b1v.x, b1v.y, b1v.z, b1v.w};
#pragma unroll
            for (int i = 0; i < 8; i++)
#pragma unroll
                for (int j = 0; j < 8; j++)
                    acc[i][j] = fmaf(av[i], bv[j], acc[i][j]);
        }
        __syncthreads();
    }
#pragma unroll
    for (int i = 0; i < 8; i++) {
        float* cp = C + (size_t)(rowb + tr + i) * N + colb + tc;
        float4 o0 = {acc[i][0], acc[i][1], acc[i][2], acc[i][3]};
        float4 o1 = {acc[i][4], acc[i][5], acc[i][6], acc[i][7]};
        *(float4*)cp       = o0;
        *(float4*)(cp + 4) = o1;
    }
}

// ===========================================================================
// Flash attention via mma.sync (HMMA bf16, split hi+lo = fp32-class accuracy).
// One CTA per (bh, 128 q-rows). 8 warps; each warp owns 16 rows (softmax
// is fully warp-local). KV tiles of 64 rows.
// ===========================================================================
#define PAD 72   // row pad: 144B = 9x16B chunks -> conflict-free ldmatrix

__global__ void __launch_bounds__(256, 1) attn_mma(const float* __restrict__ qkv,
                                                   float* __restrict__ ctx) {
    __shared__ __align__(16) uint16_t sbuf[2 * 128 * PAD];  // 36,864 B
    // aliased layouts:
    //   Q phase: Qh = sbuf[0:128*PAD), Ql = sbuf[128*PAD:...)
    //   KV phase: Kh at 0, Kl at 64*PAD, Vh at 128*PAD, Vl at 192*PAD
    const uint32_t sb = smem_to_u32(sbuf);

    int tid  = threadIdx.x;
    int lane = tid & 31;
    int w    = tid >> 5;

    int bh = blockIdx.y;
    int b = bh >> 3, h = bh & 7;
    int q0 = blockIdx.x * 128;

    const float* qp = qkv + (size_t)b * SEQN * QKVW + h * DHEAD;
    const float* kp = qp + 512;
    const float* vp = qp + 1024;

    // ---- stage Q (scaled, split) into smem
    {
        int r  = tid >> 1;
        int d0 = (tid & 1) * 32;
        const float* src = qp + (size_t)(q0 + r) * QKVW + d0;
        uint16_t* dh = sbuf + r * PAD + d0;
        uint16_t* dl = dh + 128 * PAD;
#pragma unroll
        for (int c = 0; c < 8; c++) {
            float4 f = *(const float4*)(src + 4 * c);
            f.x *= SCALE_F; f.y *= SCALE_F; f.z *= SCALE_F; f.w *= SCALE_F;
            uint32_t lo0, lo1;
            uint32_t hi0 = pack_split(f.x, f.y, lo0);
            uint32_t hi1 = pack_split(f.z, f.w, lo1);
            *(uint32_t*)(dh + 4 * c)     = hi0;
            *(uint32_t*)(dh + 4 * c + 2) = hi1;
            *(uint32_t*)(dl + 4 * c)     = lo0;
            *(uint32_t*)(dl + 4 * c + 2) = lo1;
        }
    }
    __syncthreads();

    // ---- load Q a-frags (4 k-chunks x 4 regs, hi and lo)
    uint32_t qh[4][4], ql[4][4];
    {
        int row = w * 16 + (lane & 15);
        int col = ((lane >> 4) & 1) * 8;
#pragma unroll
        for (int k = 0; k < 4; k++) {
            uint32_t a = sb + (uint32_t)(row * PAD + k * 16 + col) * 2;
            LDSM_X4(qh[k], a);
            LDSM_X4(ql[k], a + (uint32_t)(128 * PAD * 2));
        }
    }
    __syncthreads();   // Q smem now dead; reuse for K/V

    float m_prev[2] = {-1e30f, -1e30f};
    float l_prev[2] = {0.0f, 0.0f};
    float o[8][4];
#pragma unroll
    for (int n = 0; n < 8; n++)
#pragma unroll
        for (int i = 0; i < 4; i++) o[n][i] = 0.0f;

    const uint32_t uKh = sb;
    const uint32_t uKl = sb + (uint32_t)(64 * PAD * 2);
    const uint32_t uVh = sb + (uint32_t)(128 * PAD * 2);
    const uint32_t uVl = sb + (uint32_t)(192 * PAD * 2);

    for (int t = 0; t < SEQN / 64; t++) {
        int kv0 = t * 64;

        // ---- load + split K/V tile (64 rows x 64 d)
        {
            int r  = tid >> 2;
            int d0 = (tid & 3) << 4;
            const float* ks = kp + (size_t)(kv0 + r) * QKVW + d0;
            const float* vs = vp + (size_t)(kv0 + r) * QKVW + d0;
            uint16_t* kh = sbuf + r * PAD + d0;
            uint16_t* kl = kh + 64 * PAD;
            uint16_t* vh = kh + 128 * PAD;
            uint16_t* vl = kh + 192 * PAD;
#pragma unroll
            for (int c = 0; c < 4; c++) {
                float4 f = *(const float4*)(ks + 4 * c);
                uint32_t lo0, lo1;
                uint32_t hi0 = pack_split(f.x, f.y, lo0);
                uint32_t hi1 = pack_split(f.z, f.w, lo1);
                *(uint32_t*)(kh + 4 * c)     = hi0;
                *(uint32_t*)(kh + 4 * c + 2) = hi1;
                *(uint32_t*)(kl + 4 * c)     = lo0;
                *(uint32_t*)(kl + 4 * c + 2) = lo1;
                float4 g = *(const float4*)(vs + 4 * c);
                hi0 = pack_split(g.x, g.y, lo0);
                hi1 = pack_split(g.z, g.w, lo1);
                *(uint32_t*)(vh + 4 * c)     = hi0;
                *(uint32_t*)(vh + 4 * c + 2) = hi1;
                *(uint32_t*)(vl + 4 * c)     = lo0;
                *(uint32_t*)(vl + 4 * c + 2) = lo1;
            }
        }
        __syncthreads();

        // ---- S = Qs @ K^T  (split: QhKh + QlKh + QhKl)
        float s[8][4];
#pragma unroll
        for (int n = 0; n < 8; n++)
#pragma unroll
            for (int i = 0; i < 4; i++) s[n][i] = 0.0f;

        {
            int brow = lane & 7;
            int bcol = ((lane >> 3) & 1) * 8;
#pragma unroll
            for (int n = 0; n < 8; n++) {
                uint32_t abase = (uint32_t)((n * 8 + brow) * PAD + bcol) * 2;
#pragma unroll
                for (int k = 0; k < 4; k++) {
                    uint32_t a = uKh + abase + (uint32_t)(k * 32);
                    uint32_t b0, b1, c0, c1;
                    LDSM_X2(b0, b1, a);
                    mma_bf16(s[n], qh[k], b0, b1);
                    mma_bf16(s[n], ql[k], b0, b1);
                    LDSM_X2(c0, c1, a + (uint32_t)(64 * PAD * 2));
                    mma_bf16(s[n], qh[k], c0, c1);
                }
            }
        }

        // ---- online softmax (warp-local; rows live in lane quads)
        float ma = -1e30f, mb = -1e30f;
#pragma unroll
        for (int n = 0; n < 8; n++) {
            ma = fmaxf(ma, fmaxf(s[n][0], s[n][1]));
            mb = fmaxf(mb, fmaxf(s[n][2], s[n][3]));
        }
        ma = fmaxf(ma, __shfl_xor_sync(0xffffffffu, ma, 1));
        ma = fmaxf(ma, __shfl_xor_sync(0xffffffffu, ma, 2));
        mb = fmaxf(mb, __shfl_xor_sync(0xffffffffu, mb, 1));
        mb = fmaxf(mb, __shfl_xor_sync(0xffffffffu, mb, 2));
        float mnA = fmaxf(m_prev[0], ma);
        float mnB = fmaxf(m_prev[1], mb);
        float corrA = __expf(m_prev[0] - mnA);
        float corrB = __expf(m_prev[1] - mnB);
        m_prev[0] = mnA; m_prev[1] = mnB;

        float la = 0.0f, lb = 0.0f;
#pragma unroll
        for (int n = 0; n < 8; n++) {
            s[n][0] = __expf(s[n][0] - mnA);
            s[n][1] = __expf(s[n][1] - mnA);
            s[n][2] = __expf(s[n][2] - mnB);
            s[n][3] = __expf(s[n][3] - mnB);
            la += s[n][0] + s[n][1];
            lb += s[n][2] + s[n][3];
        }
        la += __shfl_xor_sync(0xffffffffu, la, 1);
        la += __shfl_xor_sync(0xffffffffu, la, 2);
        lb += __shfl_xor_sync(0xffffffffu, lb, 1);
        lb += __shfl_xor_sync(0xffffffffu, lb, 2);
        l_prev[0] = l_prev[0] * corrA + la;
        l_prev[1] = l_prev[1] * corrB + lb;

        // ---- pack P -> split-bf16 a-frags (in-register, no smem)
        uint32_t pah[4][4], pal[4][4];
#pragma unroll
        for (int kc = 0; kc < 4; kc++) {
            int j0 = 2 * kc, j1 = 2 * kc + 1;
            pah[kc][0] = pack_split(s[j0][0], s[j0][1], pal[kc][0]);
            pah[kc][1] = pack_split(s[j0][2], s[j0][3], pal[kc][1]);
            pah[kc][2] = pack_split(s[j1][0], s[j1][1], pal[kc][2]);
            pah[kc][3] = pack_split(s[j1][2], s[j1][3], pal[kc][3]);
        }

        // ---- rescale O
#pragma unroll
        for (int n = 0; n < 8; n++) {
            o[n][0] *= corrA; o[n][1] *= corrA;
            o[n][2] *= corrB; o[n][3] *= corrB;
        }

        // ---- O += P @ V  (split: PhVh + PlVh + PhVl)
        {
            int vrow = lane & 15;
#pragma unroll
            for (int nd = 0; nd < 8; nd++) {
#pragma unroll
                for (int kc = 0; kc < 4; kc++) {
                    uint32_t a = uVh + (uint32_t)((kc * 16 + vrow) * PAD + nd * 8) * 2;
                    uint32_t b0, b1, c0, c1;
                    LDSM_X2T(b0, b1, a);
                    mma_bf16(o[nd], pah[kc], b0, b1);
                    mma_bf16(o[nd], pal[kc], b0, b1);
                    LDSM_X2T(c0, c1, a + (uint32_t)(64 * PAD * 2));
                    mma_bf16(o[nd], pah[kc], c0, c1);
                }
            }
        }
        __syncthreads();   // tile consumed; next iter overwrites K/V
    }

    // ---- normalize + store context rows
    {
        float invA = 1.0f / l_prev[0];
        float invB = 1.0f / l_prev[1];
        int rowA = q0 + w * 16 + (lane >> 2);
        int colb = h * DHEAD + 2 * (lane & 3);
        float* baseA = ctx + (size_t)(b * SEQN + rowA) * DIMM + colb;
        float* baseB = baseA + (size_t)8 * DIMM;
#pragma unroll
        for (int nd = 0; nd < 8; nd++) {
            float2 oa = {o[nd][0] * invA, o[nd][1] * invA};
            float2 ob = {o[nd][2] * invB, o[nd][3] * invB};
            *(float2*)(baseA + nd * 8) = oa;
            *(float2*)(baseB + nd * 8) = ob;
        }
    }
}

// ---------------------------------------------------------------------------
// kernel_launch
// ---------------------------------------------------------------------------
extern "C" void kernel_launch(void* const* d_in, const int* in_sizes, int n_in,
                              void* d_out, int out_size) {
    const float* x     = (const float*)d_in[0];
    const float* gamma = (const float*)d_in[1];
    const float* beta  = (const float*)d_in[2];
    const float* wqkv  = (const float*)d_in[3];
    const float* wout  = (const float*)d_in[4];
    float* out = (float*)d_out;

    float *h, *qkv, *ctx;
    cudaGetSymbolAddress((void**)&h,   g_h);
    cudaGetSymbolAddress((void**)&qkv, g_qkv);
    cudaGetSymbolAddress((void**)&ctx, g_ctx);

    ln_kernel<<<NTOK, 128>>>(x, gamma, beta, h);
    sgemm128<<<dim3(QKVW / 128, NTOK / 128), 256>>>(h, wqkv, qkv, NTOK, QKVW, DIMM);
    attn_mma<<<dim3(SEQN / 128, 4 * HEADS), 256>>>(qkv, ctx);
    sgemm128<<<dim3(DIMM / 128, NTOK / 128), 256>>>(ctx, wout, out, NTOK, DIMM, DIMM);
}

// round 5
// speedup vs baseline: 1.5867x; 1.0576x over previous
#include <cuda_runtime.h>
#include <cuda_bf16.h>
#include <cstdint>

// Problem constants
#define DIMM   512
#define NTOK   8192         // B * N = 4 * 2048
#define QKVW   1536         // 3 * INNER
#define SEQN   2048
#define QSCALE 0.18033688011118042f   // 0.125 * log2(e)  (exp2 domain)

// Scratch (static device globals)
__device__ float g_h[NTOK * DIMM];     // LayerNorm output
__device__ float g_qkv[NTOK * QKVW];   // QKV projection (fp32)
__device__ float g_ctx[NTOK * DIMM];   // attention context

// Planar split-bf16 QKV: [bh=32][n=2048][d=64], 128B rows
#define PLANE_ELEMS (32 * 2048 * 64)
__device__ __align__(16) __nv_bfloat16 g_qh[PLANE_ELEMS];
__device__ __align__(16) __nv_bfloat16 g_ql[PLANE_ELEMS];
__device__ __align__(16) __nv_bfloat16 g_kh[PLANE_ELEMS];
__device__ __align__(16) __nv_bfloat16 g_kl[PLANE_ELEMS];
__device__ __align__(16) __nv_bfloat16 g_vh[PLANE_ELEMS];
__device__ __align__(16) __nv_bfloat16 g_vl[PLANE_ELEMS];

// ===========================================================================
// helpers
// ===========================================================================
__device__ __forceinline__ uint32_t smem_to_u32(const void* p) {
    uint32_t a;
    asm("{ .reg .u64 t; cvta.to.shared.u64 t, %1; cvt.u32.u64 %0, t; }" : "=r"(a) : "l"(p));
    return a;
}

__device__ __forceinline__ float ex2f(float x) {
    float y;
    asm("ex2.approx.f32 %0, %1;" : "=f"(y) : "f"(x));
    return y;
}

// split-bf16 pack: returns packed(hi(a),hi(b)), writes packed(lo(a),lo(b))
__device__ __forceinline__ uint32_t pack_split(float a, float b, uint32_t& lo) {
    __nv_bfloat16 ah = __float2bfloat16(a);
    __nv_bfloat16 bh = __float2bfloat16(b);
    __nv_bfloat16 al = __float2bfloat16(a - __bfloat162float(ah));
    __nv_bfloat16 bl = __float2bfloat16(b - __bfloat162float(bh));
    lo = (uint32_t)__bfloat16_as_ushort(al) | ((uint32_t)__bfloat16_as_ushort(bl) << 16);
    return (uint32_t)__bfloat16_as_ushort(ah) | ((uint32_t)__bfloat16_as_ushort(bh) << 16);
}

__device__ __forceinline__ void mma_bf16(float* d, const uint32_t* a, uint32_t b0, uint32_t b1) {
    asm volatile("mma.sync.aligned.m16n8k16.row.col.f32.bf16.bf16.f32 "
                 "{%0,%1,%2,%3}, {%4,%5,%6,%7}, {%8,%9}, {%0,%1,%2,%3};"
                 : "+f"(d[0]), "+f"(d[1]), "+f"(d[2]), "+f"(d[3])
                 : "r"(a[0]), "r"(a[1]), "r"(a[2]), "r"(a[3]), "r"(b0), "r"(b1));
}

#define LDSM_X4(r, a) \
    asm volatile("ldmatrix.sync.aligned.m8n8.x4.shared.b16 {%0,%1,%2,%3}, [%4];" \
        : "=r"((r)[0]), "=r"((r)[1]), "=r"((r)[2]), "=r"((r)[3]) : "r"(a))
#define LDSM_X2(r0, r1, a) \
    asm volatile("ldmatrix.sync.aligned.m8n8.x2.shared.b16 {%0,%1}, [%2];" \
        : "=r"(r0), "=r"(r1) : "r"(a))
#define LDSM_X2T(r0, r1, a) \
    asm volatile("ldmatrix.sync.aligned.m8n8.x2.trans.shared.b16 {%0,%1}, [%2];" \
        : "=r"(r0), "=r"(r1) : "r"(a))

#define CP_ASYNC16(d, s) \
    asm volatile("cp.async.cg.shared.global [%0], [%1], 16;" :: "r"(d), "l"(s) : "memory")
#define CP_COMMIT() asm volatile("cp.async.commit_group;" ::: "memory")
#define CP_WAIT1()  asm volatile("cp.async.wait_group 1;" ::: "memory")
#define CP_WAIT0()  asm volatile("cp.async.wait_group 0;" ::: "memory")

// ===========================================================================
// LayerNorm
// ===========================================================================
__global__ void __launch_bounds__(128) ln_kernel(const float* __restrict__ x,
                                                 const float* __restrict__ gamma,
                                                 const float* __restrict__ beta,
                                                 float* __restrict__ h) {
    int row = blockIdx.x;
    int tid = threadIdx.x;
    const float* xr = x + (size_t)row * DIMM;
    float4 v = *(const float4*)(xr + tid * 4);
    float s  = v.x + v.y + v.z + v.w;
    float s2 = v.x * v.x + v.y * v.y + v.z * v.z + v.w * v.w;
#pragma unroll
    for (int off = 16; off > 0; off >>= 1) {
        s  += __shfl_xor_sync(0xffffffffu, s,  off);
        s2 += __shfl_xor_sync(0xffffffffu, s2, off);
    }
    __shared__ float red[8];
    int wid = tid >> 5;
    if ((tid & 31) == 0) { red[wid] = s; red[4 + wid] = s2; }
    __syncthreads();
    float sum  = red[0] + red[1] + red[2] + red[3];
    float sum2 = red[4] + red[5] + red[6] + red[7];
    float mean = sum * (1.0f / DIMM);
    float var  = sum2 * (1.0f / DIMM) - mean * mean;
    float rstd = rsqrtf(var + 1e-5f);
    float4 g = *(const float4*)(gamma + tid * 4);
    float4 b = *(const float4*)(beta  + tid * 4);
    float4 o;
    o.x = (v.x - mean) * rstd * g.x + b.x;
    o.y = (v.y - mean) * rstd * g.y + b.y;
    o.z = (v.z - mean) * rstd * g.z + b.z;
    o.w = (v.w - mean) * rstd * g.w + b.w;
    *(float4*)(h + (size_t)row * DIMM + tid * 4) = o;
}

// ===========================================================================
// fp32 SGEMM (proven)
// ===========================================================================
__global__ void __launch_bounds__(256) sgemm128(const float* __restrict__ A,
                                                const float* __restrict__ B,
                                                float* __restrict__ C,
                                                int M, int N, int K) {
    __shared__ float As[16][128];
    __shared__ float Bs[16][128];
    int tid  = threadIdx.x;
    int rowb = blockIdx.y * 128;
    int colb = blockIdx.x * 128;
    int tr = (tid >> 4) * 8;
    int tc = (tid & 15) * 8;
    int ar = tid >> 1;
    int ak = (tid & 1) * 8;
    int br = tid >> 5;
    int bc = (tid & 31) * 4;
    const float* Ap = A + (size_t)(rowb + ar) * K + ak;
    const float* Bp = B + colb + bc;
    float acc[8][8];
#pragma unroll
    for (int i = 0; i < 8; i++)
#pragma unroll
        for (int j = 0; j < 8; j++) acc[i][j] = 0.0f;
    for (int k0 = 0; k0 < K; k0 += 16) {
        float4 a0 = *(const float4*)(Ap + k0);
        float4 a1 = *(const float4*)(Ap + k0 + 4);
        float4 b0 = *(const float4*)(Bp + (size_t)(k0 + br) * N);
        float4 b1 = *(const float4*)(Bp + (size_t)(k0 + br + 8) * N);
        As[ak + 0][ar] = a0.x; As[ak + 1][ar] = a0.y;
        As[ak + 2][ar] = a0.z; As[ak + 3][ar] = a0.w;
        As[ak + 4][ar] = a1.x; As[ak + 5][ar] = a1.y;
        As[ak + 6][ar] = a1.z; As[ak + 7][ar] = a1.w;
        *(float4*)&Bs[br][bc]     = b0;
        *(float4*)&Bs[br + 8][bc] = b1;
        __syncthreads();
#pragma unroll
        for (int k = 0; k < 16; k++) {
            float4 a0v = *(float4*)&As[k][tr];
            float4 a1v = *(float4*)&As[k][tr + 4];
            float4 b0v = *(float4*)&Bs[k][tc];
            float4 b1v = *(float4*)&Bs[k][tc + 4];
            float av[8] = {a0v.x, a0v.y, a0v.z, a0v.w, a1v.x, a1v.y, a1v.z, a1v.w};
            float bv[8] = {b0v.x, b0v.y, b0v.z, b0v.w, b1v.x, b1v.y, b1v.z, b1v.w};
#pragma unroll
            for (int i = 0; i < 8; i++)
#pragma unroll
                for (int j = 0; j < 8; j++)
                    acc[i][j] = fmaf(av[i], bv[j], acc[i][j]);
        }
        __syncthreads();
    }
#pragma unroll
    for (int i = 0; i < 8; i++) {
        float* cp = C + (size_t)(rowb + tr + i) * N + colb + tc;
        float4 o0 = {acc[i][0], acc[i][1], acc[i][2], acc[i][3]};
        float4 o1 = {acc[i][4], acc[i][5], acc[i][6], acc[i][7]};
        *(float4*)cp       = o0;
        *(float4*)(cp + 4) = o1;
    }
}

// ===========================================================================
// Split QKV fp32 -> planar split-bf16 (Q pre-scaled into exp2 domain)
// one thread per 2 elements; 24576 blocks x 256
// ===========================================================================
__global__ void __launch_bounds__(256) split_qkv(const float* __restrict__ qkv) {
    int idx = blockIdx.x * 256 + threadIdx.x;
    int tok = idx / 768;
    int p2  = idx - tok * 768;
    int col = p2 * 2;
    int tensor = col >> 9;          // 0=q 1=k 2=v
    int h = (col >> 6) & 7;
    int d = col & 63;
    int bh = ((tok >> 11) << 3) | h;
    float2 v = *(const float2*)(qkv + (size_t)tok * QKVW + col);
    if (tensor == 0) { v.x *= QSCALE; v.y *= QSCALE; }
    uint32_t lo;
    uint32_t hi = pack_split(v.x, v.y, lo);
    size_t off = ((size_t)bh * 2048 + (tok & 2047)) * 64 + d;
    if (tensor == 0) {
        *(uint32_t*)(&g_qh[off]) = hi;
        *(uint32_t*)(&g_ql[off]) = lo;
    } else if (tensor == 1) {
        *(uint32_t*)(&g_kh[off]) = hi;
        *(uint32_t*)(&g_kl[off]) = lo;
    } else {
        *(uint32_t*)(&g_vh[off]) = hi;
        *(uint32_t*)(&g_vl[off]) = lo;
    }
}

// ===========================================================================
// Flash attention: HMMA split-bf16 + cp.async double-buffered KV pipeline.
// CTA = (bh, 128 q rows), 8 warps, warp-local softmax (exp2 domain).
// smem: 2 stages x (Kh 8K | Kl 8K | Vh 8K | Vl 8K) = 64KB dynamic.
// swizzle: 128B rows, chunk c at byte ((c ^ (row&7)) << 4)
// ===========================================================================
__global__ void __launch_bounds__(256, 1) attn_mma(float* __restrict__ ctx) {
    extern __shared__ __align__(128) char smem[];
    const uint32_t sb = smem_to_u32(smem);

    int tid  = threadIdx.x;
    int lane = tid & 31;
    int w    = tid >> 5;
    int bh = blockIdx.y;
    int b = bh >> 3, h = bh & 7;
    int q0 = blockIdx.x * 128;

    size_t pb = (size_t)bh * (2048 * 64);
    const __nv_bfloat16* pqh = g_qh + pb;
    const __nv_bfloat16* pql = g_ql + pb;
    const __nv_bfloat16* pkh = g_kh + pb;
    const __nv_bfloat16* pkl = g_kl + pb;
    const __nv_bfloat16* pvh = g_vh + pb;
    const __nv_bfloat16* pvl = g_vl + pb;

    // ---- stage Q (hi rows by tid<128, lo rows by tid>=128) into stage-0 area
    {
        int r = tid & 127;
        const __nv_bfloat16* src = ((tid < 128) ? pqh : pql) + (size_t)(q0 + r) * 64;
        uint64_t gs = (uint64_t)__cvta_generic_to_global(src);
        uint32_t db = sb + ((tid < 128) ? 0u : 16384u) + (uint32_t)r * 128u;
        uint32_t swr = (uint32_t)(r & 7);
#pragma unroll
        for (int c = 0; c < 8; c++)
            CP_ASYNC16(db + (((uint32_t)c ^ swr) << 4), gs + (uint64_t)c * 16);
    }
    CP_COMMIT();
    CP_WAIT0();
    __syncthreads();

    uint32_t qh[4][4], ql[4][4];
    {
        int r = w * 16 + (lane & 15);
        int ch = (lane >> 4) & 1;
        uint32_t rb = sb + (uint32_t)r * 128u;
        uint32_t swr = (uint32_t)(r & 7);
#pragma unroll
        for (int k = 0; k < 4; k++) {
            uint32_t c = (uint32_t)(k * 2 + ch);
            uint32_t a = rb + ((c ^ swr) << 4);
            LDSM_X4(qh[k], a);
            LDSM_X4(ql[k], a + 16384u);
        }
    }
    __syncthreads();

    // KV staging parameters (per thread): plane p, row r
    int sp_p = tid >> 6;            // 0:Kh 1:Kl 2:Vh 3:Vl
    int sp_r = tid & 63;
    const __nv_bfloat16* sp_plane = (sp_p == 0) ? pkh : (sp_p == 1) ? pkl
                                   : (sp_p == 2) ? pvh : pvl;
    uint32_t sp_db = (uint32_t)(sp_p * 8192 + sp_r * 128);
    uint32_t sp_sw = (uint32_t)(sp_r & 7);

#define STAGE_KV(T, S) do { \
    uint64_t gs = (uint64_t)__cvta_generic_to_global(sp_plane + (size_t)((T) * 64 + sp_r) * 64); \
    uint32_t db = sb + (uint32_t)((S) * 32768) + sp_db; \
    _Pragma("unroll") \
    for (int c = 0; c < 8; c++) \
        CP_ASYNC16(db + (((uint32_t)c ^ sp_sw) << 4), gs + (uint64_t)c * 16); \
    CP_COMMIT(); \
} while (0)

    float m_prev[2] = {-1e30f, -1e30f};
    float l_prev[2] = {0.0f, 0.0f};
    float o[8][4];
#pragma unroll
    for (int n = 0; n < 8; n++)
#pragma unroll
        for (int i = 0; i < 4; i++) o[n][i] = 0.0f;

    STAGE_KV(0, 0);

    for (int t = 0; t < SEQN / 64; t++) {
        if (t < SEQN / 64 - 1) {
            STAGE_KV(t + 1, (t + 1) & 1);
            CP_WAIT1();
        } else {
            CP_WAIT0();
        }
        __syncthreads();

        uint32_t kb = sb + (uint32_t)((t & 1) * 32768);

        // ---- S = Qs @ K^T  (QhKh + QlKh + QhKl)
        float s[8][4];
#pragma unroll
        for (int n = 0; n < 8; n++)
#pragma unroll
            for (int i = 0; i < 4; i++) s[n][i] = 0.0f;
        {
            int brow = lane & 7;
            int bco  = (lane >> 3) & 1;
#pragma unroll
            for (int n = 0; n < 8; n++) {
                int r = n * 8 + brow;
                uint32_t rb = kb + (uint32_t)r * 128u;
                uint32_t swr = (uint32_t)(r & 7);
#pragma unroll
                for (int k = 0; k < 4; k++) {
                    uint32_t c = (uint32_t)(k * 2 + bco);
                    uint32_t a = rb + ((c ^ swr) << 4);
                    uint32_t b0, b1, c0, c1;
                    LDSM_X2(b0, b1, a);
                    mma_bf16(s[n], qh[k], b0, b1);
                    mma_bf16(s[n], ql[k], b0, b1);
                    LDSM_X2(c0, c1, a + 8192u);
                    mma_bf16(s[n], qh[k], c0, c1);
                }
            }
        }

        // ---- online softmax (exp2 domain, warp-local)
        float ma = -1e30f, mb = -1e30f;
#pragma unroll
        for (int n = 0; n < 8; n++) {
            ma = fmaxf(ma, fmaxf(s[n][0], s[n][1]));
            mb = fmaxf(mb, fmaxf(s[n][2], s[n][3]));
        }
        ma = fmaxf(ma, __shfl_xor_sync(0xffffffffu, ma, 1));
        ma = fmaxf(ma, __shfl_xor_sync(0xffffffffu, ma, 2));
        mb = fmaxf(mb, __shfl_xor_sync(0xffffffffu, mb, 1));
        mb = fmaxf(mb, __shfl_xor_sync(0xffffffffu, mb, 2));
        float mnA = fmaxf(m_prev[0], ma);
        float mnB = fmaxf(m_prev[1], mb);
        float corrA = ex2f(m_prev[0] - mnA);
        float corrB = ex2f(m_prev[1] - mnB);
        m_prev[0] = mnA; m_prev[1] = mnB;

        float la = 0.0f, lb = 0.0f;
#pragma unroll
        for (int n = 0; n < 8; n++) {
            s[n][0] = ex2f(s[n][0] - mnA);
            s[n][1] = ex2f(s[n][1] - mnA);
            s[n][2] = ex2f(s[n][2] - mnB);
            s[n][3] = ex2f(s[n][3] - mnB);
            la += s[n][0] + s[n][1];
            lb += s[n][2] + s[n][3];
        }
        la += __shfl_xor_sync(0xffffffffu, la, 1);
        la += __shfl_xor_sync(0xffffffffu, la, 2);
        lb += __shfl_xor_sync(0xffffffffu, lb, 1);
        lb += __shfl_xor_sync(0xffffffffu, lb, 2);
        l_prev[0] = l_prev[0] * corrA + la;
        l_prev[1] = l_prev[1] * corrB + lb;

        // ---- pack P -> split a-frags
        uint32_t pah[4][4], pal[4][4];
#pragma unroll
        for (int kc = 0; kc < 4; kc++) {
            int j0 = 2 * kc, j1 = 2 * kc + 1;
            pah[kc][0] = pack_split(s[j0][0], s[j0][1], pal[kc][0]);
            pah[kc][1] = pack_split(s[j0][2], s[j0][3], pal[kc][1]);
            pah[kc][2] = pack_split(s[j1][0], s[j1][1], pal[kc][2]);
            pah[kc][3] = pack_split(s[j1][2], s[j1][3], pal[kc][3]);
        }

        // ---- rescale O
#pragma unroll
        for (int n = 0; n < 8; n++) {
            o[n][0] *= corrA; o[n][1] *= corrA;
            o[n][2] *= corrB; o[n][3] *= corrB;
        }

        // ---- O += P @ V  (PhVh + PlVh + PhVl)
        {
            uint32_t vb = kb + 16384u;
            int vrow = lane & 15;
#pragma unroll
            for (int nd = 0; nd < 8; nd++) {
#pragma unroll
                for (int kc = 0; kc < 4; kc++) {
                    int r = kc * 16 + vrow;
                    uint32_t a = vb + (uint32_t)r * 128u
                               + (((uint32_t)nd ^ (uint32_t)(r & 7)) << 4);
                    uint32_t b0, b1, c0, c1;
                    LDSM_X2T(b0, b1, a);
                    mma_bf16(o[nd], pah[kc], b0, b1);
                    mma_bf16(o[nd], pal[kc], b0, b1);
                    LDSM_X2T(c0, c1, a + 8192u);
                    mma_bf16(o[nd], pah[kc], c0, c1);
                }
            }
        }
        __syncthreads();
    }

    // ---- normalize + store
    {
        float invA = 1.0f / l_prev[0];
        float invB = 1.0f / l_prev[1];
        int rowA = q0 + w * 16 + (lane >> 2);
        int colb = h * 64 + 2 * (lane & 3);
        float* baseA = ctx + (size_t)(b * SEQN + rowA) * DIMM + colb;
        float* baseB = baseA + (size_t)8 * DIMM;
#pragma unroll
        for (int nd = 0; nd < 8; nd++) {
            float2 oa = {o[nd][0] * invA, o[nd][1] * invA};
            float2 ob = {o[nd][2] * invB, o[nd][3] * invB};
            *(float2*)(baseA + nd * 8) = oa;
            *(float2*)(baseB + nd * 8) = ob;
        }
    }
}

// ---------------------------------------------------------------------------
// kernel_launch
// ---------------------------------------------------------------------------
extern "C" void kernel_launch(void* const* d_in, const int* in_sizes, int n_in,
                              void* d_out, int out_size) {
    const float* x     = (const float*)d_in[0];
    const float* gamma = (const float*)d_in[1];
    const float* beta  = (const float*)d_in[2];
    const float* wqkv  = (const float*)d_in[3];
    const float* wout  = (const float*)d_in[4];
    float* out = (float*)d_out;

    float *h, *qkv, *ctx;
    cudaGetSymbolAddress((void**)&h,   g_h);
    cudaGetSymbolAddress((void**)&qkv, g_qkv);
    cudaGetSymbolAddress((void**)&ctx, g_ctx);

    cudaFuncSetAttribute(attn_mma, cudaFuncAttributeMaxDynamicSharedMemorySize, 65536);

    ln_kernel<<<NTOK, 128>>>(x, gamma, beta, h);
    sgemm128<<<dim3(QKVW / 128, NTOK / 128), 256>>>(h, wqkv, qkv, NTOK, QKVW, DIMM);
    split_qkv<<<NTOK * QKVW / 512, 256>>>(qkv);
    attn_mma<<<dim3(16, 32), 256, 65536>>>(ctx);
    sgemm128<<<dim3(DIMM / 128, NTOK / 128), 256>>>(ctx, wout, out, NTOK, DIMM, DIMM);
}

// round 6
// speedup vs baseline: 2.1966x; 1.3844x over previous
#include <cuda_runtime.h>
#include <cuda_bf16.h>
#include <cstdint>

// Problem constants
#define DIMM   512
#define NTOK   8192         // B * N = 4 * 2048
#define QKVW   1536
#define SEQN   2048
#define QSCALE 0.18033688011118042f   // 0.125 * log2(e)  (exp2 domain)

// ---------------------------------------------------------------------------
// Device scratch (no allocations allowed anywhere)
// ---------------------------------------------------------------------------
#define PLANE_ELEMS (32 * 2048 * 64)
__device__ __align__(16) __nv_bfloat16 g_qh[PLANE_ELEMS], g_ql[PLANE_ELEMS];
__device__ __align__(16) __nv_bfloat16 g_kh[PLANE_ELEMS], g_kl[PLANE_ELEMS];
__device__ __align__(16) __nv_bfloat16 g_vh[PLANE_ELEMS], g_vl[PLANE_ELEMS];
__device__ __align__(16) __nv_bfloat16 g_hh[NTOK * DIMM], g_hl[NTOK * DIMM];     // LN out
__device__ __align__(16) __nv_bfloat16 g_cth[NTOK * DIMM], g_ctl[NTOK * DIMM];   // ctx
__device__ __align__(16) __nv_bfloat16 g_wqh[DIMM * QKVW], g_wql[DIMM * QKVW];
__device__ __align__(16) __nv_bfloat16 g_woh[DIMM * DIMM], g_wol[DIMM * DIMM];

// ===========================================================================
// helpers
// ===========================================================================
__device__ __forceinline__ uint32_t smem_to_u32(const void* p) {
    uint32_t a;
    asm("{ .reg .u64 t; cvta.to.shared.u64 t, %1; cvt.u32.u64 %0, t; }" : "=r"(a) : "l"(p));
    return a;
}
__device__ __forceinline__ float ex2f(float x) {
    float y;
    asm("ex2.approx.f32 %0, %1;" : "=f"(y) : "f"(x));
    return y;
}
__device__ __forceinline__ uint32_t pack_split(float a, float b, uint32_t& lo) {
    __nv_bfloat16 ah = __float2bfloat16(a);
    __nv_bfloat16 bh = __float2bfloat16(b);
    __nv_bfloat16 al = __float2bfloat16(a - __bfloat162float(ah));
    __nv_bfloat16 bl = __float2bfloat16(b - __bfloat162float(bh));
    lo = (uint32_t)__bfloat16_as_ushort(al) | ((uint32_t)__bfloat16_as_ushort(bl) << 16);
    return (uint32_t)__bfloat16_as_ushort(ah) | ((uint32_t)__bfloat16_as_ushort(bh) << 16);
}
__device__ __forceinline__ void mma_bf16(float* d, const uint32_t* a, uint32_t b0, uint32_t b1) {
    asm volatile("mma.sync.aligned.m16n8k16.row.col.f32.bf16.bf16.f32 "
                 "{%0,%1,%2,%3}, {%4,%5,%6,%7}, {%8,%9}, {%0,%1,%2,%3};"
                 : "+f"(d[0]), "+f"(d[1]), "+f"(d[2]), "+f"(d[3])
                 : "r"(a[0]), "r"(a[1]), "r"(a[2]), "r"(a[3]), "r"(b0), "r"(b1));
}
#define LDSM_X4(r, a) \
    asm volatile("ldmatrix.sync.aligned.m8n8.x4.shared.b16 {%0,%1,%2,%3}, [%4];" \
        : "=r"((r)[0]), "=r"((r)[1]), "=r"((r)[2]), "=r"((r)[3]) : "r"(a))
#define LDSM_X2(r0, r1, a) \
    asm volatile("ldmatrix.sync.aligned.m8n8.x2.shared.b16 {%0,%1}, [%2];" \
        : "=r"(r0), "=r"(r1) : "r"(a))
#define LDSM_X2T(r0, r1, a) \
    asm volatile("ldmatrix.sync.aligned.m8n8.x2.trans.shared.b16 {%0,%1}, [%2];" \
        : "=r"(r0), "=r"(r1) : "r"(a))
#define CP_ASYNC16(d, s) \
    asm volatile("cp.async.cg.shared.global [%0], [%1], 16;" :: "r"(d), "l"(s) : "memory")
#define CP_COMMIT() asm volatile("cp.async.commit_group;" ::: "memory")
#define CP_WAIT1()  asm volatile("cp.async.wait_group 1;" ::: "memory")
#define CP_WAIT0()  asm volatile("cp.async.wait_group 0;" ::: "memory")

// ===========================================================================
// LayerNorm -> split bf16 planes
// ===========================================================================
__global__ void __launch_bounds__(128) ln_split(const float* __restrict__ x,
                                                const float* __restrict__ gamma,
                                                const float* __restrict__ beta) {
    int row = blockIdx.x;
    int tid = threadIdx.x;
    const float* xr = x + (size_t)row * DIMM;
    float4 v = *(const float4*)(xr + tid * 4);
    float s  = v.x + v.y + v.z + v.w;
    float s2 = v.x * v.x + v.y * v.y + v.z * v.z + v.w * v.w;
#pragma unroll
    for (int off = 16; off > 0; off >>= 1) {
        s  += __shfl_xor_sync(0xffffffffu, s,  off);
        s2 += __shfl_xor_sync(0xffffffffu, s2, off);
    }
    __shared__ float red[8];
    int wid = tid >> 5;
    if ((tid & 31) == 0) { red[wid] = s; red[4 + wid] = s2; }
    __syncthreads();
    float sum  = red[0] + red[1] + red[2] + red[3];
    float sum2 = red[4] + red[5] + red[6] + red[7];
    float mean = sum * (1.0f / DIMM);
    float var  = sum2 * (1.0f / DIMM) - mean * mean;
    float rstd = rsqrtf(var + 1e-5f);
    float4 g = *(const float4*)(gamma + tid * 4);
    float4 b = *(const float4*)(beta  + tid * 4);
    float ox = (v.x - mean) * rstd * g.x + b.x;
    float oy = (v.y - mean) * rstd * g.y + b.y;
    float oz = (v.z - mean) * rstd * g.z + b.z;
    float ow = (v.w - mean) * rstd * g.w + b.w;
    uint32_t l0, l1;
    uint32_t h0 = pack_split(ox, oy, l0);
    uint32_t h1 = pack_split(oz, ow, l1);
    size_t off = (size_t)row * DIMM + tid * 4;
    *(uint2*)(&g_hh[off]) = make_uint2(h0, h1);
    *(uint2*)(&g_hl[off]) = make_uint2(l0, l1);
}

// ===========================================================================
// Split weights fp32 -> bf16 hi/lo planes
// ===========================================================================
#define WQKV_PAIRS (DIMM * QKVW / 2)
#define WOUT_PAIRS (DIMM * DIMM / 2)
__global__ void __launch_bounds__(256) split_w(const float* __restrict__ wqkv,
                                               const float* __restrict__ wout) {
    int idx = blockIdx.x * 256 + threadIdx.x;
    if (idx < WQKV_PAIRS) {
        float2 v = *(const float2*)(wqkv + (size_t)idx * 2);
        uint32_t lo, hi = pack_split(v.x, v.y, lo);
        hi = hi; // keep
        *(uint32_t*)(&g_wqh[(size_t)idx * 2]) = hi;
        *(uint32_t*)(&g_wql[(size_t)idx * 2]) = lo;
    } else {
        int j = idx - WQKV_PAIRS;
        if (j < WOUT_PAIRS) {
            float2 v = *(const float2*)(wout + (size_t)j * 2);
            uint32_t lo, hi = pack_split(v.x, v.y, lo);
            *(uint32_t*)(&g_woh[(size_t)j * 2]) = hi;
            *(uint32_t*)(&g_wol[(size_t)j * 2]) = lo;
        }
    }
}

// ===========================================================================
// Split-bf16 HMMA GEMM: C[M,N] = (Ah+Al)[M,K] @ (Bh+Bl)[K,N]
// Block 256 thr, tile 128x128, K-step 32, cp.async double buffer.
// mode 0: write fp32 C.  mode 1: QKV epilogue -> planar split q/k/v.
// smem per stage: A hi 10240 + A lo 10240 + B hi 8192 + B lo 8192 = 36864
// ===========================================================================
#define GST 36864
__global__ void __launch_bounds__(256, 2) gemm_bf16(
    const __nv_bfloat16* __restrict__ Ah, const __nv_bfloat16* __restrict__ Al,
    const __nv_bfloat16* __restrict__ Bh, const __nv_bfloat16* __restrict__ Bl,
    int N, int K, int mode, float* __restrict__ C) {
    extern __shared__ __align__(128) char smem[];
    const uint32_t sb = smem_to_u32(smem);

    int tid = threadIdx.x;
    int lane = tid & 31;
    int w = tid >> 5;
    int wm = w & 3;              // 4 m-strips of 32
    int wn = w >> 2;             // 2 n-strips of 64
    int m0 = blockIdx.y * 128;
    int n0 = blockIdx.x * 128;

    // staging params
    int sp   = tid >> 7;                 // 0=hi plane, 1=lo plane
    int ar   = tid & 127;                // A row
    int br_  = (tid & 127) >> 2;         // B row (0..31)
    int bc0  = (tid & 3) * 4;            // B first chunk
    const __nv_bfloat16* Asrc = sp ? Al : Ah;
    const __nv_bfloat16* Bsrc = sp ? Bl : Bh;

#define G_STAGE(T, S) do { \
    int k0 = (T) * 32; \
    uint32_t abase = sb + (uint32_t)((S) * GST + sp * 10240 + ar * 80); \
    uint64_t asrc = (uint64_t)__cvta_generic_to_global(Asrc + (size_t)(m0 + ar) * K + k0); \
    _Pragma("unroll") \
    for (int c = 0; c < 4; c++) CP_ASYNC16(abase + c * 16, asrc + (uint64_t)c * 16); \
    uint32_t bbase = sb + (uint32_t)((S) * GST + 20480 + sp * 8192 + br_ * 256); \
    uint64_t bsrc = (uint64_t)__cvta_generic_to_global(Bsrc + (size_t)(k0 + br_) * N + n0); \
    _Pragma("unroll") \
    for (int c = 0; c < 4; c++) { \
        uint32_t cc = (uint32_t)(bc0 + c); \
        CP_ASYNC16(bbase + ((cc ^ (uint32_t)(br_ & 7)) << 4), bsrc + (uint64_t)cc * 16); \
    } \
    CP_COMMIT(); \
} while (0)

    float acc[2][8][4];
#pragma unroll
    for (int i = 0; i < 2; i++)
#pragma unroll
        for (int j = 0; j < 8; j++)
#pragma unroll
            for (int q = 0; q < 4; q++) acc[i][j][q] = 0.0f;

    int TN = K / 32;
    G_STAGE(0, 0);
    for (int t = 0; t < TN; t++) {
        if (t < TN - 1) { G_STAGE(t + 1, (t + 1) & 1); CP_WAIT1(); }
        else CP_WAIT0();
        __syncthreads();
        uint32_t base = sb + (uint32_t)((t & 1) * GST);
#pragma unroll
        for (int kc = 0; kc < 2; kc++) {
            uint32_t ah[2][4], al[2][4];
#pragma unroll
            for (int i = 0; i < 2; i++) {
                uint32_t aaddr = base + (uint32_t)((wm * 32 + i * 16 + (lane & 15)) * 80
                               + kc * 32 + ((lane >> 4) & 1) * 16);
                LDSM_X4(ah[i], aaddr);
                LDSM_X4(al[i], aaddr + 10240u);
            }
            int kr = kc * 16 + (lane & 15);
            uint32_t bb = base + 20480u + (uint32_t)(kr * 256);
            uint32_t swr = (uint32_t)(kr & 7);
#pragma unroll
            for (int j = 0; j < 8; j++) {
                uint32_t cc = (uint32_t)(wn * 8 + j);
                uint32_t baddr = bb + ((cc ^ swr) << 4);
                uint32_t b0, b1, c0, c1;
                LDSM_X2T(b0, b1, baddr);
                LDSM_X2T(c0, c1, baddr + 8192u);
#pragma unroll
                for (int i = 0; i < 2; i++) {
                    mma_bf16(acc[i][j], ah[i], b0, b1);
                    mma_bf16(acc[i][j], al[i], b0, b1);
                    mma_bf16(acc[i][j], ah[i], c0, c1);
                }
            }
        }
        __syncthreads();
    }

    // ---- epilogue
    if (mode == 0) {
#pragma unroll
        for (int i = 0; i < 2; i++) {
            int r0 = m0 + wm * 32 + i * 16 + (lane >> 2);
#pragma unroll
            for (int j = 0; j < 8; j++) {
                int n = n0 + wn * 64 + j * 8 + 2 * (lane & 3);
                *(float2*)&C[(size_t)r0 * N + n]       = make_float2(acc[i][j][0], acc[i][j][1]);
                *(float2*)&C[(size_t)(r0 + 8) * N + n] = make_float2(acc[i][j][2], acc[i][j][3]);
            }
        }
    } else {
#pragma unroll
        for (int i = 0; i < 2; i++) {
            int r0 = m0 + wm * 32 + i * 16 + (lane >> 2);
#pragma unroll
            for (int j = 0; j < 8; j++) {
                int n = n0 + wn * 64 + j * 8 + 2 * (lane & 3);
                int tensor = n >> 9;
                int hh = (n >> 6) & 7;
                int d  = n & 63;
                __nv_bfloat16* ph = (tensor == 0) ? g_qh : (tensor == 1) ? g_kh : g_vh;
                __nv_bfloat16* pl = (tensor == 0) ? g_ql : (tensor == 1) ? g_kl : g_vl;
#pragma unroll
                for (int rr = 0; rr < 2; rr++) {
                    int row = r0 + rr * 8;
                    float xa = acc[i][j][rr * 2], xb = acc[i][j][rr * 2 + 1];
                    if (tensor == 0) { xa *= QSCALE; xb *= QSCALE; }
                    int bh = ((row >> 11) << 3) | hh;
                    size_t off = ((size_t)bh * 2048 + (row & 2047)) * 64 + d;
                    uint32_t lo, hi = pack_split(xa, xb, lo);
                    *(uint32_t*)(ph + off) = hi;
                    *(uint32_t*)(pl + off) = lo;
                }
            }
        }
    }
}

// ===========================================================================
// Flash attention: HMMA split-bf16, Q resident in smem, cp.async KV pipeline.
// smem: Qh 16K | Ql 16K | 2 stages x (Kh 8K Kl 8K Vh 8K Vl 8K) = 96KB.
// target 2 CTAs/SM.
// ===========================================================================
__global__ void __launch_bounds__(256, 2) attn_mma() {
    extern __shared__ __align__(128) char smem[];
    const uint32_t sb = smem_to_u32(smem);

    int tid  = threadIdx.x;
    int lane = tid & 31;
    int w    = tid >> 5;
    int bh = blockIdx.y;
    int b = bh >> 3, h = bh & 7;
    int q0 = blockIdx.x * 128;

    size_t pb = (size_t)bh * (2048 * 64);
    const __nv_bfloat16* pqh = g_qh + pb;
    const __nv_bfloat16* pql = g_ql + pb;
    const __nv_bfloat16* pkh = g_kh + pb;
    const __nv_bfloat16* pkl = g_kl + pb;
    const __nv_bfloat16* pvh = g_vh + pb;
    const __nv_bfloat16* pvl = g_vl + pb;

    // ---- stage Q (resident)
    {
        int r = tid & 127;
        const __nv_bfloat16* src = ((tid < 128) ? pqh : pql) + (size_t)(q0 + r) * 64;
        uint64_t gs = (uint64_t)__cvta_generic_to_global(src);
        uint32_t db = sb + ((tid < 128) ? 0u : 16384u) + (uint32_t)r * 128u;
        uint32_t swr = (uint32_t)(r & 7);
#pragma unroll
        for (int c = 0; c < 8; c++)
            CP_ASYNC16(db + (((uint32_t)c ^ swr) << 4), gs + (uint64_t)c * 16);
    }
    CP_COMMIT();

    // KV staging params
    int sp_p = tid >> 6;
    int sp_r = tid & 63;
    const __nv_bfloat16* sp_plane = (sp_p == 0) ? pkh : (sp_p == 1) ? pkl
                                   : (sp_p == 2) ? pvh : pvl;
    uint32_t sp_db = (uint32_t)(sp_p * 8192 + sp_r * 128);
    uint32_t sp_sw = (uint32_t)(sp_r & 7);

#define A_STAGE(T, S) do { \
    uint64_t gs = (uint64_t)__cvta_generic_to_global(sp_plane + (size_t)((T) * 64 + sp_r) * 64); \
    uint32_t db = sb + 32768u + (uint32_t)((S) * 32768) + sp_db; \
    _Pragma("unroll") \
    for (int c = 0; c < 8; c++) \
        CP_ASYNC16(db + (((uint32_t)c ^ sp_sw) << 4), gs + (uint64_t)c * 16); \
    CP_COMMIT(); \
} while (0)

    float m_prev[2] = {-1e30f, -1e30f};
    float l_prev[2] = {0.0f, 0.0f};
    float o[8][4];
#pragma unroll
    for (int n = 0; n < 8; n++)
#pragma unroll
        for (int i = 0; i < 4; i++) o[n][i] = 0.0f;

    A_STAGE(0, 0);
    CP_WAIT0();     // Q + stage0 both landed
    __syncthreads();

    for (int t = 0; t < SEQN / 64; t++) {
        if (t < SEQN / 64 - 1) {
            A_STAGE(t + 1, (t + 1) & 1);
            CP_WAIT1();
        } else {
            CP_WAIT0();
        }
        __syncthreads();

        uint32_t kb = sb + 32768u + (uint32_t)((t & 1) * 32768);

        // ---- S = Q @ K^T (k-outer, n-inner; Q re-LDSM'd from resident smem)
        float s[8][4];
#pragma unroll
        for (int n = 0; n < 8; n++)
#pragma unroll
            for (int i = 0; i < 4; i++) s[n][i] = 0.0f;
        {
            int qr = w * 16 + (lane & 15);
            int qch = (lane >> 4) & 1;
            uint32_t qrb = sb + (uint32_t)qr * 128u;
            uint32_t qsw = (uint32_t)(qr & 7);
            int brow = lane & 7;
            int bco  = (lane >> 3) & 1;
#pragma unroll
            for (int k = 0; k < 4; k++) {
                uint32_t qc = (uint32_t)(k * 2 + qch);
                uint32_t qaddr = qrb + ((qc ^ qsw) << 4);
                uint32_t qh[4], ql[4];
                LDSM_X4(qh, qaddr);
                LDSM_X4(ql, qaddr + 16384u);
#pragma unroll
                for (int n = 0; n < 8; n++) {
                    int r = n * 8 + brow;
                    uint32_t c = (uint32_t)(k * 2 + bco);
                    uint32_t a = kb + (uint32_t)r * 128u + ((c ^ (uint32_t)(r & 7)) << 4);
                    uint32_t b0, b1, c0, c1;
                    LDSM_X2(b0, b1, a);
                    mma_bf16(s[n], qh, b0, b1);
                    mma_bf16(s[n], ql, b0, b1);
                    LDSM_X2(c0, c1, a + 8192u);
                    mma_bf16(s[n], qh, c0, c1);
                }
            }
        }

        // ---- online softmax (exp2 domain, warp-local)
        float ma = -1e30f, mb = -1e30f;
#pragma unroll
        for (int n = 0; n < 8; n++) {
            ma = fmaxf(ma, fmaxf(s[n][0], s[n][1]));
            mb = fmaxf(mb, fmaxf(s[n][2], s[n][3]));
        }
        ma = fmaxf(ma, __shfl_xor_sync(0xffffffffu, ma, 1));
        ma = fmaxf(ma, __shfl_xor_sync(0xffffffffu, ma, 2));
        mb = fmaxf(mb, __shfl_xor_sync(0xffffffffu, mb, 1));
        mb = fmaxf(mb, __shfl_xor_sync(0xffffffffu, mb, 2));
        float mnA = fmaxf(m_prev[0], ma);
        float mnB = fmaxf(m_prev[1], mb);
        float corrA = ex2f(m_prev[0] - mnA);
        float corrB = ex2f(m_prev[1] - mnB);
        m_prev[0] = mnA; m_prev[1] = mnB;

        float la = 0.0f, lb = 0.0f;
#pragma unroll
        for (int n = 0; n < 8; n++) {
            s[n][0] = ex2f(s[n][0] - mnA);
            s[n][1] = ex2f(s[n][1] - mnA);
            s[n][2] = ex2f(s[n][2] - mnB);
            s[n][3] = ex2f(s[n][3] - mnB);
            la += s[n][0] + s[n][1];
            lb += s[n][2] + s[n][3];
        }
        la += __shfl_xor_sync(0xffffffffu, la, 1);
        la += __shfl_xor_sync(0xffffffffu, la, 2);
        lb += __shfl_xor_sync(0xffffffffu, lb, 1);
        lb += __shfl_xor_sync(0xffffffffu, lb, 2);
        l_prev[0] = l_prev[0] * corrA + la;
        l_prev[1] = l_prev[1] * corrB + lb;

        // ---- pack P -> split a-frags
        uint32_t pah[4][4], pal[4][4];
#pragma unroll
        for (int kc = 0; kc < 4; kc++) {
            int j0 = 2 * kc, j1 = 2 * kc + 1;
            pah[kc][0] = pack_split(s[j0][0], s[j0][1], pal[kc][0]);
            pah[kc][1] = pack_split(s[j0][2], s[j0][3], pal[kc][1]);
            pah[kc][2] = pack_split(s[j1][0], s[j1][1], pal[kc][2]);
            pah[kc][3] = pack_split(s[j1][2], s[j1][3], pal[kc][3]);
        }

        // ---- rescale O
#pragma unroll
        for (int n = 0; n < 8; n++) {
            o[n][0] *= corrA; o[n][1] *= corrA;
            o[n][2] *= corrB; o[n][3] *= corrB;
        }

        // ---- O += P @ V
        {
            uint32_t vb = kb + 16384u;
            int vrow = lane & 15;
#pragma unroll
            for (int nd = 0; nd < 8; nd++) {
#pragma unroll
                for (int kc = 0; kc < 4; kc++) {
                    int r = kc * 16 + vrow;
                    uint32_t a = vb + (uint32_t)r * 128u
                               + (((uint32_t)nd ^ (uint32_t)(r & 7)) << 4);
                    uint32_t b0, b1, c0, c1;
                    LDSM_X2T(b0, b1, a);
                    mma_bf16(o[nd], pah[kc], b0, b1);
                    mma_bf16(o[nd], pal[kc], b0, b1);
                    LDSM_X2T(c0, c1, a + 8192u);
                    mma_bf16(o[nd], pah[kc], c0, c1);
                }
            }
        }
        __syncthreads();
    }

    // ---- normalize + store split-bf16 ctx
    {
        float invA = 1.0f / l_prev[0];
        float invB = 1.0f / l_prev[1];
        int rowA = q0 + w * 16 + (lane >> 2);
        int colb = h * 64 + 2 * (lane & 3);
        size_t baseA = (size_t)(b * SEQN + rowA) * DIMM + colb;
        size_t baseB = baseA + (size_t)8 * DIMM;
#pragma unroll
        for (int nd = 0; nd < 8; nd++) {
            uint32_t lo, hi;
            hi = pack_split(o[nd][0] * invA, o[nd][1] * invA, lo);
            *(uint32_t*)(g_cth + baseA + nd * 8) = hi;
            *(uint32_t*)(g_ctl + baseA + nd * 8) = lo;
            hi = pack_split(o[nd][2] * invB, o[nd][3] * invB, lo);
            *(uint32_t*)(g_cth + baseB + nd * 8) = hi;
            *(uint32_t*)(g_ctl + baseB + nd * 8) = lo;
        }
    }
}

// ---------------------------------------------------------------------------
// kernel_launch
// ---------------------------------------------------------------------------
extern "C" void kernel_launch(void* const* d_in, const int* in_sizes, int n_in,
                              void* d_out, int out_size) {
    const float* x     = (const float*)d_in[0];
    const float* gamma = (const float*)d_in[1];
    const float* beta  = (const float*)d_in[2];
    const float* wqkv  = (const float*)d_in[3];
    const float* wout  = (const float*)d_in[4];
    float* out = (float*)d_out;

    __nv_bfloat16 *hh, *hl, *wqh, *wql, *woh, *wol, *cth, *ctl;
    cudaGetSymbolAddress((void**)&hh,  g_hh);
    cudaGetSymbolAddress((void**)&hl,  g_hl);
    cudaGetSymbolAddress((void**)&wqh, g_wqh);
    cudaGetSymbolAddress((void**)&wql, g_wql);
    cudaGetSymbolAddress((void**)&woh, g_woh);
    cudaGetSymbolAddress((void**)&wol, g_wol);
    cudaGetSymbolAddress((void**)&cth, g_cth);
    cudaGetSymbolAddress((void**)&ctl, g_ctl);

    static bool attrs_set = false;
    cudaFuncSetAttribute(gemm_bf16, cudaFuncAttributeMaxDynamicSharedMemorySize, 2 * GST);
    cudaFuncSetAttribute(attn_mma, cudaFuncAttributeMaxDynamicSharedMemorySize, 98304);
    (void)attrs_set;

    int wpairs = (WQKV_PAIRS + WOUT_PAIRS + 255) / 256;
    split_w<<<wpairs, 256>>>(wqkv, wout);
    ln_split<<<NTOK, 128>>>(x, gamma, beta);
    gemm_bf16<<<dim3(QKVW / 128, NTOK / 128), 256, 2 * GST>>>(hh, hl, wqh, wql,
                                                              QKVW, DIMM, 1, nullptr);
    attn_mma<<<dim3(16, 32), 256, 98304>>>();
    gemm_bf16<<<dim3(DIMM / 128, NTOK / 128), 256, 2 * GST>>>(cth, ctl, woh, wol,
                                                              DIMM, DIMM, 0, out);
}